// round 1
// baseline (speedup 1.0000x reference)
#include <cuda_runtime.h>
#include <cuda_bf16.h>

typedef unsigned long long u64;

#define BB 64           // batch
#define DD 512          // channels
#define CIN 2304
#define HW 196          // 14*14
#define NTOT (BB*HW)    // 12544

// ---------------- scratch (device globals, no allocation) ----------------
__device__ __align__(16) float g_xr[BB*DD*HW];     // reduced x,  (b, d, p)
__device__ __align__(16) float g_qt[HW*BB*DD];     // q, (p, b, c)
__device__ __align__(16) float g_kt[HW*BB*DD];     // k, (p, b, c)
__device__ __align__(16) float g_vt[HW*BB*DD];     // v, (p, b, c)
__device__ __align__(16) float g_virt[BB*DD*HW];   // attention out, (b, c, p)
__device__ __align__(16) float g_virtn[BB*DD*HW];  // groupnorm+relu out, (b, c, p)
__device__ __align__(16) float g_virt2[BB*DD*HW];  // w_conv out, (b, d, p)

// ---------------- packed f32x2 helpers ----------------
__device__ __forceinline__ u64 pack2(float x){
    u64 r; asm("mov.b64 %0, {%1, %1};" : "=l"(r) : "f"(x)); return r;
}
__device__ __forceinline__ void fma2(u64 &d, u64 a, u64 b){
    asm("fma.rn.f32x2 %0, %1, %2, %0;" : "+l"(d) : "l"(a), "l"(b));
}
__device__ __forceinline__ float2 unpack2(u64 v){
    float2 r; asm("mov.b64 {%0, %1}, %2;" : "=f"(r.x), "=f"(r.y) : "l"(v)); return r;
}

// =====================================================================
// Implicit-GEMM conv: Y[m, n] = sum_k W[m, k] * im2col(X)[k, n]
//   m: out channel (512), n = b*196 + p  (12544), k = c*TAPS + tap
//   TAPS = 1 (1x1 VALID) or 9 (3x3 SAME, pad 1)
//   outMode 0: Y[(b*512 + m)*196 + p]   (b, d, p)
//   outMode 1: Y[(p*64 + b)*512 + m]    (p, b, c)   -- for q/k/v
// =====================================================================
template<int TAPS>
__global__ __launch_bounds__(256, 2) void conv_gemm(
    const float* __restrict__ X, const float* __restrict__ Wt,
    float* __restrict__ Y, int Cin, int outMode)
{
    constexpr int BM = 128, BN = 128, BK = 8;
    const int K  = Cin * TAPS;
    const int m0 = blockIdx.y * BM;
    const int n0 = blockIdx.x * BN;
    const int tid = threadIdx.x;
    const int tx = tid & 15;
    const int ty = tid >> 4;

    __shared__ __align__(16) u64   As[2][BK][BM + 2];   // weights, lane-duplicated
    __shared__ __align__(16) float Bs[2][BK][BN];       // im2col tile

    // A (weights) load mapping: 128 rows x 8 cols, float4 per thread
    const int arow = tid >> 1;
    const int acol = (tid & 1) << 2;
    const float* aptr = Wt + (m0 + arow) * K + acol;

    // B (im2col) load mapping: 8 k-rows x 128 n-cols, 4 floats per thread
    const int bk = tid >> 5;
    const int bn = (tid & 31) << 2;
    int colB[4], colH[4], colW[4];
    #pragma unroll
    for (int i = 0; i < 4; i++){
        int n = n0 + bn + i;
        int bb = n / HW;
        int p  = n - bb * HW;
        int h  = p / 14;
        colB[i] = bb; colH[i] = h; colW[i] = p - h * 14;
    }

    u64 acc[8][4];
    #pragma unroll
    for (int i = 0; i < 8; i++)
        #pragma unroll
        for (int j = 0; j < 4; j++) acc[i][j] = 0ULL;

    const int KT = K / BK;
    float4 aPre;
    float  bPre[4];

    auto loadTiles = [&](int kt){
        aPre = *(const float4*)(aptr + kt * BK);
        int k = kt * BK + bk;
        int c, dh, dw;
        if (TAPS == 9){
            c = k / 9;
            int t = k - c * 9;
            int r = t / 3;
            dh = r - 1;
            dw = (t - r * 3) - 1;
        } else { c = k; dh = 0; dw = 0; }
        #pragma unroll
        for (int i = 0; i < 4; i++){
            int hh = colH[i] + dh, ww = colW[i] + dw;
            bool ok = (TAPS == 1) || (((unsigned)hh < 14u) & ((unsigned)ww < 14u));
            bPre[i] = ok ? __ldg(&X[(colB[i] * Cin + c) * HW + hh * 14 + ww]) : 0.f;
        }
    };
    auto storeTiles = [&](int bf){
        As[bf][acol + 0][arow] = pack2(aPre.x);
        As[bf][acol + 1][arow] = pack2(aPre.y);
        As[bf][acol + 2][arow] = pack2(aPre.z);
        As[bf][acol + 3][arow] = pack2(aPre.w);
        *(float4*)&Bs[bf][bk][bn] = make_float4(bPre[0], bPre[1], bPre[2], bPre[3]);
    };

    loadTiles(0);
    storeTiles(0);
    __syncthreads();

    int buf = 0;
    for (int kt = 0; kt < KT; kt++){
        if (kt + 1 < KT) loadTiles(kt + 1);
        #pragma unroll
        for (int kk = 0; kk < BK; kk++){
            u64 a2[8], b2[4];
            const u64* ap = &As[buf][kk][ty * 8];
            #pragma unroll
            for (int i = 0; i < 8; i++) a2[i] = ap[i];
            const u64* bp = (const u64*)&Bs[buf][kk][tx * 8];
            #pragma unroll
            for (int j = 0; j < 4; j++) b2[j] = bp[j];
            #pragma unroll
            for (int i = 0; i < 8; i++)
                #pragma unroll
                for (int j = 0; j < 4; j++)
                    fma2(acc[i][j], a2[i], b2[j]);
        }
        if (kt + 1 < KT) storeTiles(buf ^ 1);
        __syncthreads();
        buf ^= 1;
    }

    // epilogue
    int nb[8], np[8];
    #pragma unroll
    for (int j = 0; j < 8; j++){
        int n = n0 + tx * 8 + j;
        nb[j] = n / HW;
        np[j] = n - nb[j] * HW;
    }
    #pragma unroll
    for (int i = 0; i < 8; i++){
        int m = m0 + ty * 8 + i;
        #pragma unroll
        for (int j = 0; j < 4; j++){
            float2 v = unpack2(acc[i][j]);
            int j0 = 2 * j, j1 = 2 * j + 1;
            if (outMode == 0){
                Y[(nb[j0] * DD + m) * HW + np[j0]] = v.x;
                Y[(nb[j1] * DD + m) * HW + np[j1]] = v.y;
            } else {
                Y[(np[j0] * BB + nb[j0]) * DD + m] = v.x;
                Y[(np[j1] * BB + nb[j1]) * DD + m] = v.y;
            }
        }
    }
}

// =====================================================================
// Per-pixel cross-batch attention.  One block per pixel p.
//   S[i][j] = <q_i, k_j> / sqrt(512);  A = softmax_j(S);  virt_i = sum_j A[i][j] v_j
// q/k/v in (p, b, c) layout; virt written (b, c, p).
// =====================================================================
__global__ __launch_bounds__(256) void attn_kernel()
{
    __shared__ float ss[64][65];
    __shared__ __align__(16) float buf[4096];
    const int p   = blockIdx.x;
    const int tid = threadIdx.x;
    const int tx  = tid & 15, ty = tid >> 4;
    const float* qp = g_qt + p * BB * DD;
    const float* kp = g_kt + p * BB * DD;

    float acc[4][4];
    #pragma unroll
    for (int i = 0; i < 4; i++)
        #pragma unroll
        for (int j = 0; j < 4; j++) acc[i][j] = 0.f;

    const int li = tid >> 2;         // 0..63
    const int lc = (tid & 3) << 3;   // 0,8,16,24

    for (int c0 = 0; c0 < DD; c0 += 32){
        float4 q0 = *(const float4*)(qp + li * DD + c0 + lc);
        float4 q1 = *(const float4*)(qp + li * DD + c0 + lc + 4);
        float4 k0 = *(const float4*)(kp + li * DD + c0 + lc);
        float4 k1 = *(const float4*)(kp + li * DD + c0 + lc + 4);
        *(float4*)(buf + li * 32 + lc)            = q0;
        *(float4*)(buf + li * 32 + lc + 4)        = q1;
        *(float4*)(buf + 2048 + li * 32 + lc)     = k0;
        *(float4*)(buf + 2048 + li * 32 + lc + 4) = k1;
        __syncthreads();
        #pragma unroll 8
        for (int cc = 0; cc < 32; cc++){
            float a[4], bv[4];
            #pragma unroll
            for (int i = 0; i < 4; i++) a[i]  = buf[(ty * 4 + i) * 32 + cc];
            #pragma unroll
            for (int j = 0; j < 4; j++) bv[j] = buf[2048 + (tx * 4 + j) * 32 + cc];
            #pragma unroll
            for (int i = 0; i < 4; i++)
                #pragma unroll
                for (int j = 0; j < 4; j++)
                    acc[i][j] = fmaf(a[i], bv[j], acc[i][j]);
        }
        __syncthreads();
    }
    const float scale = 0.044194173824159216f;   // 1/sqrt(512)
    #pragma unroll
    for (int i = 0; i < 4; i++)
        #pragma unroll
        for (int j = 0; j < 4; j++)
            ss[ty * 4 + i][tx * 4 + j] = acc[i][j] * scale;
    __syncthreads();

    if (tid < 64){
        float m = -1e30f;
        #pragma unroll 8
        for (int j = 0; j < 64; j++) m = fmaxf(m, ss[tid][j]);
        float s = 0.f;
        #pragma unroll 8
        for (int j = 0; j < 64; j++){ float e = __expf(ss[tid][j] - m); ss[tid][j] = e; s += e; }
        float inv = 1.f / s;
        #pragma unroll 8
        for (int j = 0; j < 64; j++) ss[tid][j] *= inv;
    }
    __syncthreads();

    const float* vp = g_vt + p * BB * DD;
    const int vj = tid >> 2;          // output batch row i (and V load row)
    const int vc = (tid & 3) << 4;    // 0,16,32,48
    for (int c0 = 0; c0 < DD; c0 += 64){
        #pragma unroll
        for (int t = 0; t < 4; t++)
            *(float4*)(buf + vj * 64 + vc + 4 * t) =
                *(const float4*)(vp + vj * DD + c0 + vc + 4 * t);
        __syncthreads();
        float o[16];
        #pragma unroll
        for (int t = 0; t < 16; t++) o[t] = 0.f;
        #pragma unroll 4
        for (int j = 0; j < 64; j++){
            float a = ss[vj][j];
            #pragma unroll
            for (int t = 0; t < 4; t++){
                float4 vv = *(const float4*)(buf + j * 64 + vc + 4 * t);
                o[4 * t + 0] = fmaf(a, vv.x, o[4 * t + 0]);
                o[4 * t + 1] = fmaf(a, vv.y, o[4 * t + 1]);
                o[4 * t + 2] = fmaf(a, vv.z, o[4 * t + 2]);
                o[4 * t + 3] = fmaf(a, vv.w, o[4 * t + 3]);
            }
        }
        #pragma unroll
        for (int t = 0; t < 16; t++)
            g_virt[(vj * DD + c0 + vc + t) * HW + p] = o[t];
        __syncthreads();
    }
}

// =====================================================================
// GroupNorm (1 group == layernorm over C,H,W) + affine + ReLU.  1 block / sample.
// =====================================================================
__global__ __launch_bounds__(512) void gnorm_kernel(
    const float* __restrict__ gamma, const float* __restrict__ beta)
{
    const int b = blockIdx.x, tid = threadIdx.x;
    const float* src = g_virt  + b * (DD * HW);
    float*       dst = g_virtn + b * (DD * HW);
    float s = 0.f, s2 = 0.f;
    for (int idx = tid; idx < DD * HW; idx += 512){
        float v = src[idx]; s += v; s2 = fmaf(v, v, s2);
    }
    __shared__ float red[16], red2[16];
    #pragma unroll
    for (int o = 16; o > 0; o >>= 1){
        s  += __shfl_down_sync(~0u, s, o);
        s2 += __shfl_down_sync(~0u, s2, o);
    }
    if ((tid & 31) == 0){ red[tid >> 5] = s; red2[tid >> 5] = s2; }
    __syncthreads();
    __shared__ float sm, sr;
    if (tid == 0){
        float ts = 0.f, t2 = 0.f;
        for (int i = 0; i < 16; i++){ ts += red[i]; t2 += red2[i]; }
        float mean = ts / (float)(DD * HW);
        float var  = t2 / (float)(DD * HW) - mean * mean;
        sm = mean; sr = rsqrtf(var + 1e-5f);
    }
    __syncthreads();
    float mean = sm, rstd = sr;
    for (int idx = tid; idx < DD * HW; idx += 512){
        int c = idx / HW;
        float v = (src[idx] - mean) * rstd * gamma[c] + beta[c];
        dst[idx] = fmaxf(v, 0.f);
    }
}

// =====================================================================
// Residual add + global average pool + linear head.  1 block / sample.
//   out[b] = sum_d mean_p(xr + virt2) * w_pred[d]
// =====================================================================
__global__ __launch_bounds__(256) void pool_pred_kernel(
    const float* __restrict__ wpred, float* __restrict__ out)
{
    const int b = blockIdx.x, tid = threadIdx.x;
    float acc = 0.f;
    for (int d = tid; d < DD; d += 256){
        const float* a = g_xr    + (b * DD + d) * HW;
        const float* c = g_virt2 + (b * DD + d) * HW;
        float s = 0.f;
        #pragma unroll 4
        for (int p = 0; p < HW; p++) s += a[p] + c[p];
        acc = fmaf(s * (1.f / 196.f), wpred[d], acc);
    }
    #pragma unroll
    for (int o = 16; o > 0; o >>= 1) acc += __shfl_down_sync(~0u, acc, o);
    __shared__ float red[8];
    if ((tid & 31) == 0) red[tid >> 5] = acc;
    __syncthreads();
    if (tid == 0){
        float t = 0.f;
        for (int i = 0; i < 8; i++) t += red[i];
        out[b] = t;
    }
}

// =====================================================================
extern "C" void kernel_launch(void* const* d_in, const int* in_sizes, int n_in,
                              void* d_out, int out_size)
{
    const float* x        = (const float*)d_in[0];
    const float* w_reduce = (const float*)d_in[1];
    const float* w_q      = (const float*)d_in[2];
    const float* w_k      = (const float*)d_in[3];
    const float* w_v      = (const float*)d_in[4];
    const float* w_conv   = (const float*)d_in[5];
    const float* gamma    = (const float*)d_in[6];
    const float* beta     = (const float*)d_in[7];
    const float* w_pred   = (const float*)d_in[8];
    float* out = (float*)d_out;

    float *xr, *qt, *kt, *vt, *virtn, *virt2;
    cudaGetSymbolAddress((void**)&xr,    g_xr);
    cudaGetSymbolAddress((void**)&qt,    g_qt);
    cudaGetSymbolAddress((void**)&kt,    g_kt);
    cudaGetSymbolAddress((void**)&vt,    g_vt);
    cudaGetSymbolAddress((void**)&virtn, g_virtn);
    cudaGetSymbolAddress((void**)&virt2, g_virt2);

    dim3 grid(NTOT / 128, DD / 128);
    conv_gemm<1><<<grid, 256>>>(x,     w_reduce, xr,    CIN, 0);
    conv_gemm<9><<<grid, 256>>>(xr,    w_q,      qt,    DD,  1);
    conv_gemm<9><<<grid, 256>>>(xr,    w_k,      kt,    DD,  1);
    conv_gemm<9><<<grid, 256>>>(xr,    w_v,      vt,    DD,  1);
    attn_kernel<<<HW, 256>>>();
    gnorm_kernel<<<BB, 512>>>(gamma, beta);
    conv_gemm<9><<<grid, 256>>>(virtn, w_conv,   virt2, DD,  0);
    pool_pred_kernel<<<BB, 256>>>(w_pred, out);
}

// round 2
// speedup vs baseline: 1.0184x; 1.0184x over previous
#include <cuda_runtime.h>
#include <cuda_bf16.h>

typedef unsigned long long u64;

#define BB 64           // batch
#define DD 512          // channels
#define CIN 2304
#define HW 196          // 14*14
#define NTOT (BB*HW)    // 12544

// ---------------- scratch (device globals, no allocation) ----------------
__device__ __align__(16) float g_xr[BB*DD*HW];     // reduced x,  (b, d, p)
__device__ __align__(16) float g_qt[HW*BB*DD];     // q, (p, b, c)
__device__ __align__(16) float g_kt[HW*BB*DD];     // k, (p, b, c)
__device__ __align__(16) float g_vt[HW*BB*DD];     // v, (p, b, c)
__device__ __align__(16) float g_virt[BB*DD*HW];   // attention out, (b, c, p)
__device__ __align__(16) float g_virtn[BB*DD*HW];  // groupnorm+relu out, (b, c, p)
__device__ __align__(16) float g_virt2[BB*DD*HW];  // w_conv out, (b, d, p)

// ---------------- packed f32x2 helpers ----------------
__device__ __forceinline__ u64 pack2(float x){
    u64 r; asm("mov.b64 %0, {%1, %1};" : "=l"(r) : "f"(x)); return r;
}
__device__ __forceinline__ void fma2(u64 &d, u64 a, u64 b){
    asm("fma.rn.f32x2 %0, %1, %2, %0;" : "+l"(d) : "l"(a), "l"(b));
}
__device__ __forceinline__ float2 unpack2(u64 v){
    float2 r; asm("mov.b64 {%0, %1}, %2;" : "=f"(r.x), "=f"(r.y) : "l"(v)); return r;
}

// =====================================================================
// Implicit-GEMM conv: Y[m, n] = sum_k W[m, k] * im2col(X)[k, n]
//   m: out channel (512), n = b*196 + p  (12544), k = c*TAPS + tap
//   TAPS = 1 (1x1 VALID) or 9 (3x3 SAME, pad 1)
//   outMode 0: Y[(b*512 + m)*196 + p]   (b, d, p)
//   outMode 1: Y[(p*64 + b)*512 + m]    (p, b, c)   -- for q/k/v
// =====================================================================
template<int TAPS>
__global__ __launch_bounds__(256, 2) void conv_gemm(
    const float* __restrict__ X, const float* __restrict__ Wt,
    float* __restrict__ Y, int Cin, int outMode)
{
    constexpr int BM = 128, BN = 128, BK = 8;
    const int K  = Cin * TAPS;
    const int m0 = blockIdx.y * BM;
    const int n0 = blockIdx.x * BN;
    const int tid = threadIdx.x;
    const int tx = tid & 15;
    const int ty = tid >> 4;

    __shared__ __align__(16) u64   As[2][BK][BM + 2];   // weights, lane-duplicated
    __shared__ __align__(16) float Bs[2][BK][BN];       // im2col tile

    // A (weights) load mapping: 128 rows x 8 cols, float4 per thread
    const int arow = tid >> 1;
    const int acol = (tid & 1) << 2;
    const float* aptr = Wt + (m0 + arow) * K + acol;

    // B (im2col) load mapping: 8 k-rows x 128 n-cols, 4 floats per thread
    const int bk = tid >> 5;
    const int bn = (tid & 31) << 2;
    int colB[4], colH[4], colW[4];
    #pragma unroll
    for (int i = 0; i < 4; i++){
        int n = n0 + bn + i;
        int bb = n / HW;
        int p  = n - bb * HW;
        int h  = p / 14;
        colB[i] = bb; colH[i] = h; colW[i] = p - h * 14;
    }

    u64 acc[8][4];
    #pragma unroll
    for (int i = 0; i < 8; i++)
        #pragma unroll
        for (int j = 0; j < 4; j++) acc[i][j] = 0ULL;

    const int KT = K / BK;
    float4 aPre;
    float  bPre[4];

    auto loadTiles = [&](int kt){
        aPre = *(const float4*)(aptr + kt * BK);
        int k = kt * BK + bk;
        int c, dh, dw;
        if (TAPS == 9){
            c = k / 9;
            int t = k - c * 9;
            int r = t / 3;
            dh = r - 1;
            dw = (t - r * 3) - 1;
        } else { c = k; dh = 0; dw = 0; }
        #pragma unroll
        for (int i = 0; i < 4; i++){
            int hh = colH[i] + dh, ww = colW[i] + dw;
            bool ok = (TAPS == 1) || (((unsigned)hh < 14u) & ((unsigned)ww < 14u));
            bPre[i] = ok ? __ldg(&X[(colB[i] * Cin + c) * HW + hh * 14 + ww]) : 0.f;
        }
    };
    auto storeTiles = [&](int bf){
        As[bf][acol + 0][arow] = pack2(aPre.x);
        As[bf][acol + 1][arow] = pack2(aPre.y);
        As[bf][acol + 2][arow] = pack2(aPre.z);
        As[bf][acol + 3][arow] = pack2(aPre.w);
        *(float4*)&Bs[bf][bk][bn] = make_float4(bPre[0], bPre[1], bPre[2], bPre[3]);
    };

    loadTiles(0);
    storeTiles(0);
    __syncthreads();

    int buf = 0;
    for (int kt = 0; kt < KT; kt++){
        if (kt + 1 < KT) loadTiles(kt + 1);
        #pragma unroll
        for (int kk = 0; kk < BK; kk++){
            u64 a2[8], b2[4];
            const u64* ap = &As[buf][kk][ty * 8];
            #pragma unroll
            for (int i = 0; i < 8; i++) a2[i] = ap[i];
            const u64* bp = (const u64*)&Bs[buf][kk][tx * 8];
            #pragma unroll
            for (int j = 0; j < 4; j++) b2[j] = bp[j];
            #pragma unroll
            for (int i = 0; i < 8; i++)
                #pragma unroll
                for (int j = 0; j < 4; j++)
                    fma2(acc[i][j], a2[i], b2[j]);
        }
        if (kt + 1 < KT) storeTiles(buf ^ 1);
        __syncthreads();
        buf ^= 1;
    }

    // epilogue
    int nb[8], np[8];
    #pragma unroll
    for (int j = 0; j < 8; j++){
        int n = n0 + tx * 8 + j;
        nb[j] = n / HW;
        np[j] = n - nb[j] * HW;
    }
    #pragma unroll
    for (int i = 0; i < 8; i++){
        int m = m0 + ty * 8 + i;
        #pragma unroll
        for (int j = 0; j < 4; j++){
            float2 v = unpack2(acc[i][j]);
            int j0 = 2 * j, j1 = 2 * j + 1;
            if (outMode == 0){
                Y[(nb[j0] * DD + m) * HW + np[j0]] = v.x;
                Y[(nb[j1] * DD + m) * HW + np[j1]] = v.y;
            } else {
                Y[(np[j0] * BB + nb[j0]) * DD + m] = v.x;
                Y[(np[j1] * BB + nb[j1]) * DD + m] = v.y;
            }
        }
    }
}

// =====================================================================
// Per-pixel cross-batch attention.  One block per pixel p.
//   S[i][j] = <q_i, k_j> / sqrt(512);  A = softmax_j(S);  virt_i = sum_j A[i][j] v_j
// q/k/v in (p, b, c) layout; virt written (b, c, p).
// =====================================================================
__global__ __launch_bounds__(256) void attn_kernel()
{
    __shared__ float ss[64][65];
    __shared__ __align__(16) float buf[4096];
    const int p   = blockIdx.x;
    const int tid = threadIdx.x;
    const int tx  = tid & 15, ty = tid >> 4;
    const float* qp = g_qt + p * BB * DD;
    const float* kp = g_kt + p * BB * DD;

    float acc[4][4];
    #pragma unroll
    for (int i = 0; i < 4; i++)
        #pragma unroll
        for (int j = 0; j < 4; j++) acc[i][j] = 0.f;

    const int li = tid >> 2;         // 0..63
    const int lc = (tid & 3) << 3;   // 0,8,16,24

    for (int c0 = 0; c0 < DD; c0 += 32){
        float4 q0 = *(const float4*)(qp + li * DD + c0 + lc);
        float4 q1 = *(const float4*)(qp + li * DD + c0 + lc + 4);
        float4 k0 = *(const float4*)(kp + li * DD + c0 + lc);
        float4 k1 = *(const float4*)(kp + li * DD + c0 + lc + 4);
        *(float4*)(buf + li * 32 + lc)            = q0;
        *(float4*)(buf + li * 32 + lc + 4)        = q1;
        *(float4*)(buf + 2048 + li * 32 + lc)     = k0;
        *(float4*)(buf + 2048 + li * 32 + lc + 4) = k1;
        __syncthreads();
        #pragma unroll 8
        for (int cc = 0; cc < 32; cc++){
            float a[4], bv[4];
            #pragma unroll
            for (int i = 0; i < 4; i++) a[i]  = buf[(ty * 4 + i) * 32 + cc];
            #pragma unroll
            for (int j = 0; j < 4; j++) bv[j] = buf[2048 + (tx * 4 + j) * 32 + cc];
            #pragma unroll
            for (int i = 0; i < 4; i++)
                #pragma unroll
                for (int j = 0; j < 4; j++)
                    acc[i][j] = fmaf(a[i], bv[j], acc[i][j]);
        }
        __syncthreads();
    }
    const float scale = 0.044194173824159216f;   // 1/sqrt(512)
    #pragma unroll
    for (int i = 0; i < 4; i++)
        #pragma unroll
        for (int j = 0; j < 4; j++)
            ss[ty * 4 + i][tx * 4 + j] = acc[i][j] * scale;
    __syncthreads();

    if (tid < 64){
        float m = -1e30f;
        #pragma unroll 8
        for (int j = 0; j < 64; j++) m = fmaxf(m, ss[tid][j]);
        float s = 0.f;
        #pragma unroll 8
        for (int j = 0; j < 64; j++){ float e = __expf(ss[tid][j] - m); ss[tid][j] = e; s += e; }
        float inv = 1.f / s;
        #pragma unroll 8
        for (int j = 0; j < 64; j++) ss[tid][j] *= inv;
    }
    __syncthreads();

    const float* vp = g_vt + p * BB * DD;
    const int vj = tid >> 2;          // output batch row i (and V load row)
    const int vc = (tid & 3) << 4;    // 0,16,32,48
    for (int c0 = 0; c0 < DD; c0 += 64){
        #pragma unroll
        for (int t = 0; t < 4; t++)
            *(float4*)(buf + vj * 64 + vc + 4 * t) =
                *(const float4*)(vp + vj * DD + c0 + vc + 4 * t);
        __syncthreads();
        float o[16];
        #pragma unroll
        for (int t = 0; t < 16; t++) o[t] = 0.f;
        #pragma unroll 4
        for (int j = 0; j < 64; j++){
            float a = ss[vj][j];
            #pragma unroll
            for (int t = 0; t < 4; t++){
                float4 vv = *(const float4*)(buf + j * 64 + vc + 4 * t);
                o[4 * t + 0] = fmaf(a, vv.x, o[4 * t + 0]);
                o[4 * t + 1] = fmaf(a, vv.y, o[4 * t + 1]);
                o[4 * t + 2] = fmaf(a, vv.z, o[4 * t + 2]);
                o[4 * t + 3] = fmaf(a, vv.w, o[4 * t + 3]);
            }
        }
        #pragma unroll
        for (int t = 0; t < 16; t++)
            g_virt[(vj * DD + c0 + vc + t) * HW + p] = o[t];
        __syncthreads();
    }
}

// =====================================================================
// GroupNorm (1 group == layernorm over C,H,W) + affine + ReLU.  1 block / sample.
// =====================================================================
__global__ __launch_bounds__(512) void gnorm_kernel(
    const float* __restrict__ gamma, const float* __restrict__ beta)
{
    const int b = blockIdx.x, tid = threadIdx.x;
    const float* src = g_virt  + b * (DD * HW);
    float*       dst = g_virtn + b * (DD * HW);
    float s = 0.f, s2 = 0.f;
    for (int idx = tid; idx < DD * HW; idx += 512){
        float v = src[idx]; s += v; s2 = fmaf(v, v, s2);
    }
    __shared__ float red[16], red2[16];
    #pragma unroll
    for (int o = 16; o > 0; o >>= 1){
        s  += __shfl_down_sync(~0u, s, o);
        s2 += __shfl_down_sync(~0u, s2, o);
    }
    if ((tid & 31) == 0){ red[tid >> 5] = s; red2[tid >> 5] = s2; }
    __syncthreads();
    __shared__ float sm, sr;
    if (tid == 0){
        float ts = 0.f, t2 = 0.f;
        for (int i = 0; i < 16; i++){ ts += red[i]; t2 += red2[i]; }
        float mean = ts / (float)(DD * HW);
        float var  = t2 / (float)(DD * HW) - mean * mean;
        sm = mean; sr = rsqrtf(var + 1e-5f);
    }
    __syncthreads();
    float mean = sm, rstd = sr;
    for (int idx = tid; idx < DD * HW; idx += 512){
        int c = idx / HW;
        float v = (src[idx] - mean) * rstd * gamma[c] + beta[c];
        dst[idx] = fmaxf(v, 0.f);
    }
}

// =====================================================================
// Residual add + global average pool + linear head.  1 block / sample.
//   out[b] = sum_d mean_p(xr + virt2) * w_pred[d]
// =====================================================================
__global__ __launch_bounds__(256) void pool_pred_kernel(
    const float* __restrict__ wpred, float* __restrict__ out)
{
    const int b = blockIdx.x, tid = threadIdx.x;
    float acc = 0.f;
    for (int d = tid; d < DD; d += 256){
        const float* a = g_xr    + (b * DD + d) * HW;
        const float* c = g_virt2 + (b * DD + d) * HW;
        float s = 0.f;
        #pragma unroll 4
        for (int p = 0; p < HW; p++) s += a[p] + c[p];
        acc = fmaf(s * (1.f / 196.f), wpred[d], acc);
    }
    #pragma unroll
    for (int o = 16; o > 0; o >>= 1) acc += __shfl_down_sync(~0u, acc, o);
    __shared__ float red[8];
    if ((tid & 31) == 0) red[tid >> 5] = acc;
    __syncthreads();
    if (tid == 0){
        float t = 0.f;
        for (int i = 0; i < 8; i++) t += red[i];
        out[b] = t;
    }
}

// =====================================================================
extern "C" void kernel_launch(void* const* d_in, const int* in_sizes, int n_in,
                              void* d_out, int out_size)
{
    const float* x        = (const float*)d_in[0];
    const float* w_reduce = (const float*)d_in[1];
    const float* w_q      = (const float*)d_in[2];
    const float* w_k      = (const float*)d_in[3];
    const float* w_v      = (const float*)d_in[4];
    const float* w_conv   = (const float*)d_in[5];
    const float* gamma    = (const float*)d_in[6];
    const float* beta     = (const float*)d_in[7];
    const float* w_pred   = (const float*)d_in[8];
    float* out = (float*)d_out;

    float *xr, *qt, *kt, *vt, *virtn, *virt2;
    cudaGetSymbolAddress((void**)&xr,    g_xr);
    cudaGetSymbolAddress((void**)&qt,    g_qt);
    cudaGetSymbolAddress((void**)&kt,    g_kt);
    cudaGetSymbolAddress((void**)&vt,    g_vt);
    cudaGetSymbolAddress((void**)&virtn, g_virtn);
    cudaGetSymbolAddress((void**)&virt2, g_virt2);

    dim3 grid(NTOT / 128, DD / 128);
    conv_gemm<1><<<grid, 256>>>(x,     w_reduce, xr,    CIN, 0);
    conv_gemm<9><<<grid, 256>>>(xr,    w_q,      qt,    DD,  1);
    conv_gemm<9><<<grid, 256>>>(xr,    w_k,      kt,    DD,  1);
    conv_gemm<9><<<grid, 256>>>(xr,    w_v,      vt,    DD,  1);
    attn_kernel<<<HW, 256>>>();
    gnorm_kernel<<<BB, 512>>>(gamma, beta);
    conv_gemm<9><<<grid, 256>>>(virtn, w_conv,   virt2, DD,  0);
    pool_pred_kernel<<<BB, 256>>>(w_pred, out);
}